// round 13
// baseline (speedup 1.0000x reference)
#include <cuda_runtime.h>
#include <cuda_bf16.h>
#include <stdint.h>

#define BB 4
#define NN 2048
#define MM 8192
#define DD 128
#define SS 1024     // NUM_SEGMENTS
#define HB 8        // source chunks per batch, 1024 rows each
#define HBT 2       // target chunks per batch, 1024 rows each
#define NSRC_BLKS (BB * HB)            // 32
#define NTGT_BLKS (BB * HBT)           // 8
#define NBLK (NSRC_BLKS + NTGT_BLKS)   // 40
#define CAP 16                         // per-(chunk,segment) slot capacity
#define SLOT_S (HB * CAP)              // 128 ints per (b,seg) source slot
#define SLOT_T (HBT * CAP)             // 32 ints per (b,seg) target slot

// ---------------- scratch (static __device__, no allocation) ----------------
__device__ int g_rows_s[BB * SS * SLOT_S];   // 2 MB  slotted source rows
__device__ int g_rows_t[BB * SS * SLOT_T];   // 512KB slotted target rows
__device__ int g_cnt_s[BB * HB * SS];        // per-(b,chunk,seg) counts
__device__ int g_cnt_t[BB * HBT * SS];

// ---------------- 1) slotted sort: NO hist, NO scan ----------------
__global__ __launch_bounds__(256) void k_sort(const int* __restrict__ idx_src,
                                              const int* __restrict__ idx_tgt) {
    __shared__ int cur[SS];
    const int t = threadIdx.x;

    const int* in;
    int* rows;
    int* cnt_out;
    int  slot_shift;
    int  chunk;
    if (blockIdx.x < NSRC_BLKS) {
        int b = blockIdx.x >> 3, j = blockIdx.x & 7;
        in   = idx_src + b * MM + j * 1024;
        rows = g_rows_s + (size_t)b * SS * SLOT_S;
        cnt_out = g_cnt_s + (b * HB + j) * SS;
        slot_shift = 7; chunk = j;
    } else {
        int u = blockIdx.x - NSRC_BLKS;
        int b = u >> 1, j = u & 1;
        in   = idx_tgt + b * NN + j * 1024;
        rows = g_rows_t + (size_t)b * SS * SLOT_T;
        cnt_out = g_cnt_t + (b * HBT + j) * SS;
        slot_shift = 5; chunk = j;
    }

    ((int4*)cur)[t] = make_int4(0, 0, 0, 0);
    __syncthreads();

    const int4 a = ((const int4*)in)[t];
    const int m = chunk * 1024 + 4 * t;
    const int sub = chunk * CAP;
    int q;
    q = atomicAdd(&cur[a.x], 1); if (q < CAP) rows[(a.x << slot_shift) + sub + q] = m + 0;
    q = atomicAdd(&cur[a.y], 1); if (q < CAP) rows[(a.y << slot_shift) + sub + q] = m + 1;
    q = atomicAdd(&cur[a.z], 1); if (q < CAP) rows[(a.z << slot_shift) + sub + q] = m + 2;
    q = atomicAdd(&cur[a.w], 1); if (q < CAP) rows[(a.w << slot_shift) + sub + q] = m + 3;
    __syncthreads();

    ((int4*)cnt_out)[t] = ((int4*)cur)[t];   // final cursors == counts
}

// ---------------- 2) segsum + write: one BLOCK (4 warps) per segment ---------------
// bookkeeping once per block; payload rows striped warp w -> rows w::4
__global__ __launch_bounds__(128) void k_segsum_write(const float* __restrict__ src,
                                                      float* __restrict__ out,
                                                      const int* __restrict__ idx_src,
                                                      const int* __restrict__ idx_tgt) {
    __shared__ int    raw[SLOT_S];      // staged source slot (128 ints)
    __shared__ int    trw[SLOT_T];      // staged target slot (32 ints)
    __shared__ int    cpt[SLOT_S];      // compacted source rows
    __shared__ float4 part[4][32];      // per-warp partial sums

    const int tid  = threadIdx.x;
    const int lane = tid & 31;
    const int w    = tid >> 5;
    const int seg  = blockIdx.x;                 // 0..BB*SS-1
    const int b    = seg >> 10;
    const int sloc = seg & (SS - 1);

    // ---- all index loads in one parallel wave ----
    int c_s = 0, c_t = 0;
    if (lane < HB)  c_s = g_cnt_s[(b * HB  + lane) * SS + sloc];   // redundant per warp (cheap)
    if (lane < HBT) c_t = g_cnt_t[(b * HBT + lane) * SS + sloc];
    raw[tid] = g_rows_s[((size_t)seg << 7) + tid];                 // 512B coalesced
    if (tid < SLOT_T) trw[tid] = g_rows_t[((size_t)seg << 5) + tid];

    int ct0 = __shfl_sync(0xffffffffu, c_t, 0);
    int ct1 = __shfl_sync(0xffffffffu, c_t, 1);
    if (ct0 + ct1 == 0) return;                  // block-uniform

    int cj[HB], pj[HB];
    int cnt = 0;
    bool ovf = (ct0 > CAP) | (ct1 > CAP);
    #pragma unroll
    for (int j = 0; j < HB; j++) {
        cj[j] = __shfl_sync(0xffffffffu, c_s, j);
        pj[j] = cnt;
        cnt += cj[j];
        ovf |= (cj[j] > CAP);
    }

    const float* base = src + (size_t)b * MM * DD;
    float4 acc = {0.f, 0.f, 0.f, 0.f};

    if (!ovf) {
        __syncthreads();                          // raw/trw staged
        // each warp redundantly compacts (same values -> benign) then reads after its own syncwarp
        if (lane < HB) {
            int c = cj[lane], p = pj[lane];
            const int* s = raw + lane * CAP;
            for (int r = 0; r < c; r++) cpt[p + r] = s[r];
        }
        __syncwarp();

        // payload: warp w sums rows w, w+4, w+8, ... (float4 per lane, 512B/row)
        int r = w;
        for (; r + 4 < cnt; r += 8) {             // 2 rows in flight
            int m0 = cpt[r], m1 = cpt[r + 4];
            float4 v0 = ((const float4*)(base + (size_t)m0 * DD))[lane];
            float4 v1 = ((const float4*)(base + (size_t)m1 * DD))[lane];
            acc.x += v0.x + v1.x; acc.y += v0.y + v1.y;
            acc.z += v0.z + v1.z; acc.w += v0.w + v1.w;
        }
        if (r < cnt) {
            int m = cpt[r];
            float4 v = ((const float4*)(base + (size_t)m * DD))[lane];
            acc.x += v.x; acc.y += v.y; acc.z += v.z; acc.w += v.w;
        }
    } else {
        // overflow fallback (P ~ 1e-10): warp w scans a quarter of the raw indices
        const int* is = idx_src + b * MM;
        for (int i0 = w * (MM / 4); i0 < (w + 1) * (MM / 4); i0 += 32) {
            int id = is[i0 + lane];
            unsigned mask = __ballot_sync(0xffffffffu, id == sloc);
            while (mask) {
                int bit = __ffs(mask) - 1;
                mask &= mask - 1;
                float4 v = ((const float4*)(base + (size_t)(i0 + bit) * DD))[lane];
                acc.x += v.x; acc.y += v.y; acc.z += v.z; acc.w += v.w;
            }
        }
    }

    part[w][lane] = acc;
    __syncthreads();

    // every warp combines redundantly (4 shared loads) so all can help write
    float4 t0 = part[0][lane], t1 = part[1][lane], t2 = part[2][lane], t3 = part[3][lane];
    float inv = 1.0f / ((float)cnt + 1e-10f);
    float4 res;
    res.x = (t0.x + t1.x + t2.x + t3.x) * inv;
    res.y = (t0.y + t1.y + t2.y + t3.y) * inv;
    res.z = (t0.z + t1.z + t2.z + t3.z) * inv;
    res.w = (t0.w + t1.w + t2.w + t3.w) * inv;

    float* outb = out + (size_t)b * NN * DD;
    if (!ovf) {
        for (int r = w; r < ct0; r += 4) {
            int n = trw[r];
            ((float4*)(outb + (size_t)n * DD))[lane] = res;
        }
        for (int r = w; r < ct1; r += 4) {
            int n = trw[CAP + r];
            ((float4*)(outb + (size_t)n * DD))[lane] = res;
        }
    } else {
        const int* it = idx_tgt + b * NN;
        for (int i0 = w * (NN / 4); i0 < (w + 1) * (NN / 4); i0 += 32) {
            int id = it[i0 + lane];
            unsigned mask = __ballot_sync(0xffffffffu, id == sloc);
            while (mask) {
                int bit = __ffs(mask) - 1;
                mask &= mask - 1;
                ((float4*)(outb + (size_t)(i0 + bit) * DD))[lane] = res;
            }
        }
    }
}

// ---------------- launch ----------------
extern "C" void kernel_launch(void* const* d_in, const int* in_sizes, int n_in,
                              void* d_out, int out_size) {
    const int*   idx_tgt = (const int*)d_in[0];
    const int*   idx_src = (const int*)d_in[1];
    const float* src     = (const float*)d_in[2];
    float*       out     = (float*)d_out;

    k_sort        <<<NBLK, 256>>>(idx_src, idx_tgt);
    k_segsum_write<<<BB * SS, 128>>>(src, out, idx_src, idx_tgt);
}

// round 14
// speedup vs baseline: 1.4031x; 1.4031x over previous
#include <cuda_runtime.h>
#include <cuda_bf16.h>
#include <stdint.h>

#define BB 4
#define NN 2048
#define MM 8192
#define DD 128
#define SS 1024     // NUM_SEGMENTS
#define HB 8        // source chunks per batch, 1024 rows each
#define HBT 2       // target chunks per batch, 1024 rows each
#define NSRC_BLKS (BB * HB)            // 32
#define NTGT_BLKS (BB * HBT)           // 8
#define NBLK (NSRC_BLKS + NTGT_BLKS)   // 40
#define CAP 16                         // per-(chunk,segment) slot capacity
#define SLOT_S (HB * CAP)              // 128 ints per (b,seg) source slot
#define SLOT_T (HBT * CAP)             // 32 ints per (b,seg) target slot

// ---------------- scratch (static __device__, no allocation) ----------------
__device__ int g_rows_s[BB * SS * SLOT_S];   // 2 MB  slotted source rows
__device__ int g_rows_t[BB * SS * SLOT_T];   // 512KB slotted target rows
__device__ int g_cnt_s[BB * HB * SS];        // per-(b,chunk,seg) counts
__device__ int g_cnt_t[BB * HBT * SS];

// ---------------- 1) slotted sort: NO hist, NO scan ----------------
__global__ __launch_bounds__(256) void k_sort(const int* __restrict__ idx_src,
                                              const int* __restrict__ idx_tgt) {
    __shared__ int cur[SS];
    const int t = threadIdx.x;

    const int* in;
    int* rows;
    int* cnt_out;
    int  slot_shift;
    int  chunk;
    if (blockIdx.x < NSRC_BLKS) {
        int b = blockIdx.x >> 3, j = blockIdx.x & 7;
        in   = idx_src + b * MM + j * 1024;
        rows = g_rows_s + (size_t)b * SS * SLOT_S;
        cnt_out = g_cnt_s + (b * HB + j) * SS;
        slot_shift = 7; chunk = j;
    } else {
        int u = blockIdx.x - NSRC_BLKS;
        int b = u >> 1, j = u & 1;
        in   = idx_tgt + b * NN + j * 1024;
        rows = g_rows_t + (size_t)b * SS * SLOT_T;
        cnt_out = g_cnt_t + (b * HBT + j) * SS;
        slot_shift = 5; chunk = j;
    }

    ((int4*)cur)[t] = make_int4(0, 0, 0, 0);
    __syncthreads();

    const int4 a = ((const int4*)in)[t];
    const int m = chunk * 1024 + 4 * t;
    const int sub = chunk * CAP;
    int q;
    q = atomicAdd(&cur[a.x], 1); if (q < CAP) rows[(a.x << slot_shift) + sub + q] = m + 0;
    q = atomicAdd(&cur[a.y], 1); if (q < CAP) rows[(a.y << slot_shift) + sub + q] = m + 1;
    q = atomicAdd(&cur[a.z], 1); if (q < CAP) rows[(a.z << slot_shift) + sub + q] = m + 2;
    q = atomicAdd(&cur[a.w], 1); if (q < CAP) rows[(a.w << slot_shift) + sub + q] = m + 3;
    __syncthreads();

    ((int4*)cnt_out)[t] = ((int4*)cur)[t];   // final cursors == counts

    // PDL: all stores above are visible to the dependent grid after trigger
    cudaTriggerProgrammaticLaunchCompletion();
}

// ---------------- 2) segsum + write: one warp per segment (round-12 shape) ---------
__global__ __launch_bounds__(256) void k_segsum_write(const float* __restrict__ src,
                                                      float* __restrict__ out,
                                                      const int* __restrict__ idx_src,
                                                      const int* __restrict__ idx_tgt) {
    __shared__ int raw[8][SLOT_S];       // staged source slot
    __shared__ int trw[8][SLOT_T];       // staged target slot
    __shared__ int cpt[8][SLOT_S];       // compacted source rows
    int seg  = (blockIdx.x * blockDim.x + threadIdx.x) >> 5;   // 0..BB*SS-1
    int lane = threadIdx.x & 31;
    int w    = (threadIdx.x >> 5) & 7;

    // PDL: wait for k_sort's stores before consuming them
    cudaGridDependencySynchronize();

    if (seg >= BB * SS) return;
    int b    = seg >> 10;
    int sloc = seg & (SS - 1);

    // ---- ALL index loads issued in one parallel wave (no dependent hops) ----
    int c_s = 0, c_t = 0;
    if (lane < HB)  c_s = g_cnt_s[(b * HB  + lane) * SS + sloc];
    if (lane < HBT) c_t = g_cnt_t[(b * HBT + lane) * SS + sloc];
    int4 rv = ((const int4*)(g_rows_s + ((size_t)seg << 7)))[lane];   // 128 ints
    int  tv = (g_rows_t + ((size_t)seg << 5))[lane];                   // 32 ints

    int ct0 = __shfl_sync(0xffffffffu, c_t, 0);
    int ct1 = __shfl_sync(0xffffffffu, c_t, 1);
    int tcnt = ct0 + ct1;
    if (tcnt == 0) return;

    int cj[HB], pj[HB];
    int cnt = 0;
    bool ovf = (ct0 > CAP) | (ct1 > CAP);
    #pragma unroll
    for (int j = 0; j < HB; j++) {
        cj[j] = __shfl_sync(0xffffffffu, c_s, j);
        pj[j] = cnt;
        cnt += cj[j];
        ovf |= (cj[j] > CAP);
    }

    const float* base = src + (size_t)b * MM * DD;
    float4 acc0 = {0,0,0,0}, acc1 = {0,0,0,0}, acc2 = {0,0,0,0}, acc3 = {0,0,0,0};

    if (!ovf) {
        // stage slots to shared, compact chunk sub-lists
        ((int4*)raw[w])[lane] = rv;
        trw[w][lane] = tv;
        __syncwarp();
        if (lane < HB) {
            int c = cj[lane], p = pj[lane];
            const int* s = raw[w] + lane * CAP;
            for (int r = 0; r < c; r++) cpt[w][p + r] = s[r];
        }
        __syncwarp();

        const int* mlist = cpt[w];
        int r = 0;
        for (; r + 8 <= cnt; r += 8) {
            int m0 = mlist[r],   m1 = mlist[r+1], m2 = mlist[r+2], m3 = mlist[r+3];
            int m4 = mlist[r+4], m5 = mlist[r+5], m6 = mlist[r+6], m7 = mlist[r+7];
            float4 v0 = ((const float4*)(base + (size_t)m0 * DD))[lane];
            float4 v1 = ((const float4*)(base + (size_t)m1 * DD))[lane];
            float4 v2 = ((const float4*)(base + (size_t)m2 * DD))[lane];
            float4 v3 = ((const float4*)(base + (size_t)m3 * DD))[lane];
            float4 v4 = ((const float4*)(base + (size_t)m4 * DD))[lane];
            float4 v5 = ((const float4*)(base + (size_t)m5 * DD))[lane];
            float4 v6 = ((const float4*)(base + (size_t)m6 * DD))[lane];
            float4 v7 = ((const float4*)(base + (size_t)m7 * DD))[lane];
            acc0.x += v0.x + v4.x; acc0.y += v0.y + v4.y; acc0.z += v0.z + v4.z; acc0.w += v0.w + v4.w;
            acc1.x += v1.x + v5.x; acc1.y += v1.y + v5.y; acc1.z += v1.z + v5.z; acc1.w += v1.w + v5.w;
            acc2.x += v2.x + v6.x; acc2.y += v2.y + v6.y; acc2.z += v2.z + v6.z; acc2.w += v2.w + v6.w;
            acc3.x += v3.x + v7.x; acc3.y += v3.y + v7.y; acc3.z += v3.z + v7.z; acc3.w += v3.w + v7.w;
        }
        for (; r + 4 <= cnt; r += 4) {
            int m0 = mlist[r], m1 = mlist[r+1], m2 = mlist[r+2], m3 = mlist[r+3];
            float4 v0 = ((const float4*)(base + (size_t)m0 * DD))[lane];
            float4 v1 = ((const float4*)(base + (size_t)m1 * DD))[lane];
            float4 v2 = ((const float4*)(base + (size_t)m2 * DD))[lane];
            float4 v3 = ((const float4*)(base + (size_t)m3 * DD))[lane];
            acc0.x += v0.x; acc0.y += v0.y; acc0.z += v0.z; acc0.w += v0.w;
            acc1.x += v1.x; acc1.y += v1.y; acc1.z += v1.z; acc1.w += v1.w;
            acc2.x += v2.x; acc2.y += v2.y; acc2.z += v2.z; acc2.w += v2.w;
            acc3.x += v3.x; acc3.y += v3.y; acc3.z += v3.z; acc3.w += v3.w;
        }
        for (; r < cnt; r++) {
            int m = mlist[r];
            float4 v = ((const float4*)(base + (size_t)m * DD))[lane];
            acc0.x += v.x; acc0.y += v.y; acc0.z += v.z; acc0.w += v.w;
        }
    } else {
        // overflow fallback (P ~ 1e-10): ballot-scan the raw source indices
        const int* is = idx_src + b * MM;
        for (int i0 = 0; i0 < MM; i0 += 32) {
            int id = is[i0 + lane];
            unsigned mask = __ballot_sync(0xffffffffu, id == sloc);
            while (mask) {
                int bit = __ffs(mask) - 1;
                mask &= mask - 1;
                float4 v = ((const float4*)(base + (size_t)(i0 + bit) * DD))[lane];
                acc0.x += v.x; acc0.y += v.y; acc0.z += v.z; acc0.w += v.w;
            }
        }
    }

    float inv = 1.0f / ((float)cnt + 1e-10f);
    float4 res;
    res.x = (acc0.x + acc1.x + acc2.x + acc3.x) * inv;
    res.y = (acc0.y + acc1.y + acc2.y + acc3.y) * inv;
    res.z = (acc0.z + acc1.z + acc2.z + acc3.z) * inv;
    res.w = (acc0.w + acc1.w + acc2.w + acc3.w) * inv;

    float* outb = out + (size_t)b * NN * DD;
    if (!ovf) {
        for (int r = 0; r < ct0; r++) {
            int n = trw[w][r];
            ((float4*)(outb + (size_t)n * DD))[lane] = res;
        }
        for (int r = 0; r < ct1; r++) {
            int n = trw[w][CAP + r];
            ((float4*)(outb + (size_t)n * DD))[lane] = res;
        }
    } else {
        // target fallback: scan raw target indices
        const int* it = idx_tgt + b * NN;
        for (int i0 = 0; i0 < NN; i0 += 32) {
            int id = it[i0 + lane];
            unsigned mask = __ballot_sync(0xffffffffu, id == sloc);
            while (mask) {
                int bit = __ffs(mask) - 1;
                mask &= mask - 1;
                ((float4*)(outb + (size_t)(i0 + bit) * DD))[lane] = res;
            }
        }
    }
}

// ---------------- launch (PDL-chained) ----------------
extern "C" void kernel_launch(void* const* d_in, const int* in_sizes, int n_in,
                              void* d_out, int out_size) {
    const int*   idx_tgt = (const int*)d_in[0];
    const int*   idx_src = (const int*)d_in[1];
    const float* src     = (const float*)d_in[2];
    float*       out     = (float*)d_out;

    k_sort<<<NBLK, 256>>>(idx_src, idx_tgt);

    // dependent launch: overlap segsum's launch/prologue with k_sort's tail
    cudaLaunchConfig_t cfg = {};
    cfg.gridDim  = dim3((BB * SS * 32 + 255) / 256, 1, 1);
    cfg.blockDim = dim3(256, 1, 1);
    cudaLaunchAttribute attr[1];
    attr[0].id = cudaLaunchAttributeProgrammaticStreamSerialization;
    attr[0].val.programmaticStreamSerializationAllowed = 1;
    cfg.attrs = attr;
    cfg.numAttrs = 1;
    cudaLaunchKernelEx(&cfg, k_segsum_write, src, out, idx_src, idx_tgt);
}